// round 1
// baseline (speedup 1.0000x reference)
#include <cuda_runtime.h>
#include <math.h>

#define HDIM 128
#define WDIM 128
#define HW (HDIM*WDIM)
#define CDIM 256
#define BDIM 4
#define NHEAD 16
#define HDHEAD 16
#define EPS 1e-5f

// ---------------- scratch (device globals; no allocation allowed) -------------
__device__ float g_qh  [BDIM*CDIM*HW];
__device__ float g_kh  [BDIM*CDIM*HW];
__device__ float g_high[BDIM*CDIM*HW];
__device__ float g_qkv [BDIM*3*CDIM*HW];
__device__ float g_low [BDIM*CDIM*HW];
__device__ float g_mix [BDIM*CDIM*HW];
__device__ float g_sm  [BDIM*CDIM*HW];
__device__ float g_dw  [BDIM*CDIM*HW];
__device__ float g_pool[BDIM*2*HW];
__device__ float g_sig [BDIM*2*HW];

// ---------------- 1x1 conv as SGEMM: out[oc,p] = sum_ic W[oc,ic]*in[ic,p] ----
// Tile: 64 oc x 256 px per block, 256 threads, 8x8 register tile, K-chunk 16.
__global__ __launch_bounds__(256, 2)
void gemm1x1_kernel(const float* __restrict__ in, const float* __restrict__ w,
                    const float* __restrict__ bng, const float* __restrict__ bnb,
                    const float* __restrict__ bnm, const float* __restrict__ bnv,
                    float* __restrict__ out, int OC)
{
    __shared__ float sX[16*256];
    __shared__ float sW[64*16];
    const int bb  = blockIdx.z;
    const int ocT = blockIdx.y;
    const int p0  = blockIdx.x * 256;
    const int t   = threadIdx.x;
    const int col = t & 31, ocg = t >> 5;

    float acc[8][8];
#pragma unroll
    for (int i = 0; i < 8; i++)
#pragma unroll
        for (int r = 0; r < 8; r++) acc[i][r] = 0.f;

    const float* inb = in + (size_t)bb * CDIM * HW;

    for (int ic0 = 0; ic0 < CDIM; ic0 += 16) {
#pragma unroll
        for (int j = 0; j < 16; j++) {
            int e = t + j * 256;
            int ic = e >> 8, p = e & 255;
            sX[e] = inb[(ic0 + ic) * HW + p0 + p];
        }
#pragma unroll
        for (int j = 0; j < 4; j++) {
            int e = t + j * 256;
            int oc = e >> 4, ic = e & 15;
            sW[e] = w[(ocT * 64 + oc) * CDIM + ic0 + ic];
        }
        __syncthreads();
#pragma unroll
        for (int ic = 0; ic < 16; ic++) {
            float wr[8], xr[8];
#pragma unroll
            for (int i = 0; i < 8; i++) wr[i] = sW[(ocg * 8 + i) * 16 + ic];
#pragma unroll
            for (int r = 0; r < 8; r++) xr[r] = sX[ic * 256 + col + 32 * r];
#pragma unroll
            for (int i = 0; i < 8; i++)
#pragma unroll
                for (int r = 0; r < 8; r++) acc[i][r] += wr[i] * xr[r];
        }
        __syncthreads();
    }

#pragma unroll
    for (int i = 0; i < 8; i++) {
        int oc = ocT * 64 + ocg * 8 + i;
        float sc = 1.f, sh = 0.f;
        if (bng) { sc = bng[oc] * rsqrtf(bnv[oc] + EPS); sh = bnb[oc] - bnm[oc] * sc; }
#pragma unroll
        for (int r = 0; r < 8; r++) {
            float v = acc[i][r] * sc + sh;
            out[((size_t)bb * OC + oc) * HW + p0 + col + 32 * r] = v;
        }
    }
}

// ---------------- direct KxK conv 256->256 + BN (KS = 3 or 5) ---------------
// Tile: 64 oc x (8h x 32w) per block; 256 threads; 8oc x 8row register tile.
template<int KS, bool ADD_HIGH>
__global__ __launch_bounds__(256, 2)
void conv_dir_kernel(const float* __restrict__ in, const float* __restrict__ wgt,
                     const float* __restrict__ bng, const float* __restrict__ bnb,
                     const float* __restrict__ bnm, const float* __restrict__ bnv,
                     float* __restrict__ out,
                     const float* __restrict__ khbuf, float* __restrict__ out2)
{
    constexpr int PAD = KS / 2;
    constexpr int TH = 8, TW = 32, ICB = 4;
    constexpr int PH = TH + KS - 1, PW = TW + KS - 1;
    constexpr int KKS = KS * KS;

    __shared__ float sIn[ICB * PH * PW];
    __shared__ float sW[64 * ICB * KKS];

    const int w0 = blockIdx.x * TW;
    const int h0 = blockIdx.y * TH;
    const int bb  = blockIdx.z >> 2;
    const int ocT = blockIdx.z & 3;
    const int t = threadIdx.x;
    const int col = t & 31, ocg = t >> 5;

    float acc[8][8];
#pragma unroll
    for (int i = 0; i < 8; i++)
#pragma unroll
        for (int r = 0; r < 8; r++) acc[i][r] = 0.f;

    for (int ic0 = 0; ic0 < CDIM; ic0 += ICB) {
        for (int e = t; e < ICB * PH * PW; e += 256) {
            int icb = e / (PH * PW), rem = e % (PH * PW);
            int row = rem / PW, cc = rem % PW;
            int h = h0 + row - PAD, w = w0 + cc - PAD;
            float v = 0.f;
            if (h >= 0 && h < HDIM && w >= 0 && w < WDIM)
                v = in[((size_t)(bb * CDIM + ic0 + icb) * HDIM + h) * WDIM + w];
            sIn[e] = v;
        }
        for (int e = t; e < 64 * ICB * KKS; e += 256) {
            int oc = e / (ICB * KKS), rem = e % (ICB * KKS);
            int icb = rem / KKS, kk = rem % KKS;
            sW[e] = wgt[((size_t)(ocT * 64 + oc) * CDIM + ic0 + icb) * KKS + kk];
        }
        __syncthreads();
#pragma unroll
        for (int icb = 0; icb < ICB; icb++)
#pragma unroll
            for (int ky = 0; ky < KS; ky++)
#pragma unroll
                for (int kx = 0; kx < KS; kx++) {
                    float wr[8], xr[8];
#pragma unroll
                    for (int i = 0; i < 8; i++)
                        wr[i] = sW[(ocg * 8 + i) * (ICB * KKS) + icb * KKS + ky * KS + kx];
#pragma unroll
                    for (int r = 0; r < 8; r++)
                        xr[r] = sIn[icb * PH * PW + (r + ky) * PW + col + kx];
#pragma unroll
                    for (int i = 0; i < 8; i++)
#pragma unroll
                        for (int r = 0; r < 8; r++) acc[i][r] += wr[i] * xr[r];
                }
        __syncthreads();
    }

#pragma unroll
    for (int i = 0; i < 8; i++) {
        int oc = ocT * 64 + ocg * 8 + i;
        float sc = bng[oc] * rsqrtf(bnv[oc] + EPS);
        float sh = bnb[oc] - bnm[oc] * sc;
#pragma unroll
        for (int r = 0; r < 8; r++) {
            size_t idx = ((size_t)(bb * CDIM + oc) * HDIM + h0 + r) * WDIM + w0 + col;
            float v = acc[i][r] * sc + sh;
            out[idx] = v;
            if (ADD_HIGH) out2[idx] = v + khbuf[idx];
        }
    }
}

// ---------------- window attention: one block per (window, head) -------------
__global__ __launch_bounds__(64)
void attn_kernel(const float* __restrict__ qkv, const float* __restrict__ qh,
                 const float* __restrict__ kh, const float* __restrict__ rel_table,
                 float* __restrict__ low)
{
    __shared__ float sK[64 * 16];
    __shared__ float sV[64 * 16];
    __shared__ float sKH[64 * 16];
    __shared__ float sRT[225];

    const int wi = blockIdx.x;      // window within image
    const int head = blockIdx.y;
    const int bb = blockIdx.z;
    const int hh = wi >> 4, ww = wi & 15;
    const int n = threadIdx.x;      // query token 0..63
    const int rn = n >> 3, cn = n & 7;
    const int hq = hh * 8 + rn, wq = ww * 8 + cn;

    // load this thread's m-row of K, V, KH into smem; own q/qh row to registers
    const int hm = hq, wm = wq;     // token m == n for the load
    float qr[16], qhr[16];
#pragma unroll
    for (int d = 0; d < 16; d++) {
        int ch = head * 16 + d;
        sK [n * 16 + d] = qkv[((size_t)(bb * 768 + 256 + ch) * HDIM + hm) * WDIM + wm];
        sV [n * 16 + d] = qkv[((size_t)(bb * 768 + 512 + ch) * HDIM + hm) * WDIM + wm];
        sKH[n * 16 + d] = kh [((size_t)(bb * CDIM + ch) * HDIM + hm) * WDIM + wm];
        qr [d] = qkv[((size_t)(bb * 768 + ch) * HDIM + hq) * WDIM + wq];
        qhr[d] = qh [((size_t)(bb * CDIM + ch) * HDIM + hq) * WDIM + wq];
    }
    for (int i = n; i < 225; i += 64) sRT[i] = rel_table[i * NHEAD + head];
    __syncthreads();

    const float scale = 0.25f;  // HD^-0.5
    float dots[64];
#pragma unroll
    for (int m = 0; m < 64; m++) {
        float d0 = 0.f;
#pragma unroll
        for (int d = 0; d < 16; d++)
            d0 += qr[d] * sK[m * 16 + d] + qhr[d] * sKH[m * 16 + d];
        int rm = m >> 3, cm = m & 7;
        int idx = (rn - rm + 7) * 15 + (cn - cm + 7);
        dots[m] = d0 * scale + sRT[idx];
    }
    float mx = -1e30f;
#pragma unroll
    for (int m = 0; m < 64; m++) mx = fmaxf(mx, dots[m]);
    float sum = 0.f;
#pragma unroll
    for (int m = 0; m < 64; m++) { float e = __expf(dots[m] - mx); sum += e; dots[m] = e; }
    float inv = 1.f / sum;
    float o[16];
#pragma unroll
    for (int d = 0; d < 16; d++) o[d] = 0.f;
#pragma unroll
    for (int m = 0; m < 64; m++) {
        float p = dots[m] * inv;
#pragma unroll
        for (int d = 0; d < 16; d++) o[d] += p * sV[m * 16 + d];
    }
#pragma unroll
    for (int d = 0; d < 16; d++)
        low[((size_t)(bb * CDIM + head * 16 + d) * HDIM + hq) * WDIM + wq] = o[d];
}

// ---------------- channel mean/max pool per pixel ----------------------------
__global__ void pool_kernel(const float* __restrict__ low, const float* __restrict__ high,
                            float* __restrict__ pool)
{
    int p = blockIdx.x * 256 + threadIdx.x;
    int bb = blockIdx.y;
    const float* lb = low  + (size_t)bb * CDIM * HW;
    const float* hb = high + (size_t)bb * CDIM * HW;
    float s = 0.f, mx = -1e30f;
    for (int c = 0; c < CDIM; c++) {
        float v = lb[c * HW + p] + hb[c * HW + p];
        s += v; mx = fmaxf(mx, v);
    }
    pool[(bb * 2 + 0) * HW + p] = s * (1.f / 256.f);
    pool[(bb * 2 + 1) * HW + p] = mx;
}

// ---------------- hybrid 7x7 conv (2->2) + sigmoid ---------------------------
__global__ void hybrid_kernel(const float* __restrict__ pool, const float* __restrict__ hw,
                              const float* __restrict__ hb, float* __restrict__ sig)
{
    __shared__ float sw[196];
    __shared__ float sb[2];
    int t = threadIdx.x;
    if (t < 196) sw[t] = hw[t];
    if (t < 2) sb[t] = hb[t];
    __syncthreads();
    int p = blockIdx.x * 256 + t;
    int bb = blockIdx.y;
    int h = p >> 7, w = p & 127;
#pragma unroll
    for (int oc = 0; oc < 2; oc++) {
        float acc = sb[oc];
#pragma unroll
        for (int ic = 0; ic < 2; ic++)
            for (int ky = 0; ky < 7; ky++) {
                int hy = h + ky - 3;
                if (hy < 0 || hy >= HDIM) continue;
                for (int kx = 0; kx < 7; kx++) {
                    int wx = w + kx - 3;
                    if (wx < 0 || wx >= WDIM) continue;
                    acc += pool[(bb * 2 + ic) * HW + hy * WDIM + wx] * sw[((oc * 2 + ic) * 7 + ky) * 7 + kx];
                }
            }
        sig[(bb * 2 + oc) * HW + p] = 1.f / (1.f + __expf(-acc));
    }
}

// ---------------- mix: out = low*sig0 + high*sig1 ----------------------------
__global__ void mix_kernel(const float* __restrict__ low, const float* __restrict__ high,
                           const float* __restrict__ sig, float* __restrict__ out)
{
    int idx = blockIdx.x * 256 + threadIdx.x;
    int p = idx & (HW - 1);
    int bb = idx >> 22;   // idx / (256*16384)
    float s0 = sig[(bb * 2 + 0) * HW + p];
    float s1 = sig[(bb * 2 + 1) * HW + p];
    out[idx] = low[idx] * s0 + high[idx] * s1;
}

// ---------------- depthwise 7x7 + BN -----------------------------------------
__global__ void dw_kernel(const float* __restrict__ in, const float* __restrict__ w,
                          const float* __restrict__ bng, const float* __restrict__ bnb,
                          const float* __restrict__ bnm, const float* __restrict__ bnv,
                          float* __restrict__ out)
{
    __shared__ float sT[14 * 38];
    __shared__ float sWc[49];
    const int w0 = blockIdx.x * 32;
    const int h0 = blockIdx.y * 8;
    const int bc = blockIdx.z;           // b*256 + c
    const int c = bc & 255;
    const int tx = threadIdx.x, ty = threadIdx.y;
    const int t = ty * 32 + tx;
    if (t < 49) sWc[t] = w[c * 49 + t];
    const float* inb = in + (size_t)bc * HW;
    for (int e = t; e < 14 * 38; e += 256) {
        int row = e / 38, cc = e % 38;
        int h = h0 + row - 3, ww = w0 + cc - 3;
        float v = 0.f;
        if (h >= 0 && h < HDIM && ww >= 0 && ww < WDIM) v = inb[h * WDIM + ww];
        sT[e] = v;
    }
    __syncthreads();
    float acc = 0.f;
#pragma unroll
    for (int ky = 0; ky < 7; ky++)
#pragma unroll
        for (int kx = 0; kx < 7; kx++)
            acc += sT[(ty + ky) * 38 + tx + kx] * sWc[ky * 7 + kx];
    float sc = bng[c] * rsqrtf(bnv[c] + EPS);
    float sh = bnb[c] - bnm[c] * sc;
    out[(size_t)bc * HW + (h0 + ty) * WDIM + w0 + tx] = acc * sc + sh;
}

// ---------------- launch ------------------------------------------------------
extern "C" void kernel_launch(void* const* d_in, const int* in_sizes, int n_in,
                              void* d_out, int out_size)
{
    const float* x        = (const float*)d_in[0];
    const float* qkv_w    = (const float*)d_in[1];
    const float* local1_w = (const float*)d_in[2];
    const float* l1g = (const float*)d_in[3];
    const float* l1b = (const float*)d_in[4];
    const float* l1m = (const float*)d_in[5];
    const float* l1v = (const float*)d_in[6];
    const float* local2_w = (const float*)d_in[7];
    const float* l2g = (const float*)d_in[8];
    const float* l2b = (const float*)d_in[9];
    const float* l2m = (const float*)d_in[10];
    const float* l2v = (const float*)d_in[11];
    const float* rel_table = (const float*)d_in[12];
    const float* hybrid_w  = (const float*)d_in[13];
    const float* hybrid_b  = (const float*)d_in[14];
    const float* smooth_w  = (const float*)d_in[15];
    const float* smg = (const float*)d_in[16];
    const float* smb = (const float*)d_in[17];
    const float* smm = (const float*)d_in[18];
    const float* smv = (const float*)d_in[19];
    const float* proj_dw_w = (const float*)d_in[20];
    const float* prg = (const float*)d_in[21];
    const float* prb = (const float*)d_in[22];
    const float* prm = (const float*)d_in[23];
    const float* prv = (const float*)d_in[24];
    const float* proj_pw_w = (const float*)d_in[25];

    float *p_qh, *p_kh, *p_high, *p_qkv, *p_low, *p_mix, *p_sm, *p_dw, *p_pool, *p_sig;
    cudaGetSymbolAddress((void**)&p_qh,   g_qh);
    cudaGetSymbolAddress((void**)&p_kh,   g_kh);
    cudaGetSymbolAddress((void**)&p_high, g_high);
    cudaGetSymbolAddress((void**)&p_qkv,  g_qkv);
    cudaGetSymbolAddress((void**)&p_low,  g_low);
    cudaGetSymbolAddress((void**)&p_mix,  g_mix);
    cudaGetSymbolAddress((void**)&p_sm,   g_sm);
    cudaGetSymbolAddress((void**)&p_dw,   g_dw);
    cudaGetSymbolAddress((void**)&p_pool, g_pool);
    cudaGetSymbolAddress((void**)&p_sig,  g_sig);

    // qkv = 1x1 conv (768 oc)
    gemm1x1_kernel<<<dim3(64, 12, 4), 256>>>(x, qkv_w, nullptr, nullptr, nullptr, nullptr, p_qkv, 768);
    // k_h = BN(1x1 conv)
    gemm1x1_kernel<<<dim3(64, 4, 4), 256>>>(x, local2_w, l2g, l2b, l2m, l2v, p_kh, 256);
    // q_h = BN(3x3 conv); also high = q_h + k_h
    conv_dir_kernel<3, true><<<dim3(4, 16, 16), 256>>>(x, local1_w, l1g, l1b, l1m, l1v,
                                                       p_qh, p_kh, p_high);
    // window attention -> low_freq
    attn_kernel<<<dim3(256, 16, 4), 64>>>(p_qkv, p_qh, p_kh, rel_table, p_low);
    // channel pool
    pool_kernel<<<dim3(64, 4), 256>>>(p_low, p_high, p_pool);
    // hybrid gate
    hybrid_kernel<<<dim3(64, 4), 256>>>(p_pool, hybrid_w, hybrid_b, p_sig);
    // mix
    mix_kernel<<<dim3(BDIM * CDIM * HW / 256), 256>>>(p_low, p_high, p_sig, p_mix);
    // smooth 5x5 + BN
    conv_dir_kernel<5, false><<<dim3(4, 16, 16), 256>>>(p_mix, smooth_w, smg, smb, smm, smv,
                                                        p_sm, nullptr, nullptr);
    // depthwise 7x7 + BN
    dw_kernel<<<dim3(4, 16, 1024), dim3(32, 8)>>>(p_sm, proj_dw_w, prg, prb, prm, prv, p_dw);
    // final pointwise 1x1 -> d_out
    gemm1x1_kernel<<<dim3(64, 4, 4), 256>>>(p_dw, proj_pw_w, nullptr, nullptr, nullptr, nullptr,
                                            (float*)d_out, 256);
}

// round 2
// speedup vs baseline: 2.6013x; 2.6013x over previous
#include <cuda_runtime.h>
#include <math.h>
#include <stdint.h>

#define HDIM 128
#define WDIM 128
#define HW (HDIM*WDIM)
#define CDIM 256
#define BDIM 4
#define NHEAD 16
#define EPS 1e-5f

// ---------------- scratch ----------------------------------------------------
__device__ float g_qh  [BDIM*CDIM*HW];
__device__ float g_kh  [BDIM*CDIM*HW];
__device__ float g_high[BDIM*CDIM*HW];
__device__ float g_qkv [BDIM*3*CDIM*HW];
__device__ float g_low [BDIM*CDIM*HW];
__device__ float g_mix [BDIM*CDIM*HW];
__device__ float g_sm  [BDIM*CDIM*HW];
__device__ float g_dw  [BDIM*CDIM*HW];
__device__ float g_pool[BDIM*2*HW];
__device__ float g_sig [BDIM*2*HW];

// ---------------- tf32 helpers ----------------------------------------------
__device__ __forceinline__ float f2tf(float f) {
    uint32_t u;
    asm("cvt.rna.tf32.f32 %0, %1;" : "=r"(u) : "f"(f));
    return __uint_as_float(u);
}

__device__ __forceinline__ void mma_tf32(float* d, uint32_t a0, uint32_t a1,
                                         uint32_t a2, uint32_t a3,
                                         uint32_t b0, uint32_t b1) {
    asm volatile(
        "mma.sync.aligned.m16n8k8.row.col.f32.tf32.tf32.f32 "
        "{%0,%1,%2,%3}, {%4,%5,%6,%7}, {%8,%9}, {%0,%1,%2,%3};"
        : "+f"(d[0]), "+f"(d[1]), "+f"(d[2]), "+f"(d[3])
        : "r"(a0), "r"(a1), "r"(a2), "r"(a3), "r"(b0), "r"(b1));
}

// ---------------- 1x1 conv as tf32 tensor-core GEMM --------------------------
// Block: 64 oc x 256 px, 256 threads (8 warps), warp tile 32 oc x 64 px.
// K chunks of 32 (4 mma k-steps). SMEM strides chosen conflict-free.
#define XSTR 264   // 256 px + 8 pad  (ic-row stride; 264 % 32 == 8)
#define WSTR 36    // 32 ic + 4 pad

__global__ __launch_bounds__(256, 2)
void gemm1x1_mma(const float* __restrict__ in, const float* __restrict__ w,
                 const float* __restrict__ bng, const float* __restrict__ bnb,
                 const float* __restrict__ bnm, const float* __restrict__ bnv,
                 float* __restrict__ out, int OC)
{
    __shared__ float sX[32 * XSTR];
    __shared__ float sW[64 * WSTR];

    const int bb  = blockIdx.z;
    const int ocT = blockIdx.y;
    const int p0  = blockIdx.x * 256;
    const int t   = threadIdx.x;
    const int warp = t >> 5, lane = t & 31;
    const int g = lane >> 2, tg = lane & 3;
    const int wm = warp >> 2;          // 0..1 -> oc base wm*32
    const int wn = warp & 3;           // 0..3 -> px base wn*64

    float acc[2][8][4];
#pragma unroll
    for (int i = 0; i < 2; i++)
#pragma unroll
        for (int j = 0; j < 8; j++)
#pragma unroll
            for (int c = 0; c < 4; c++) acc[i][j][c] = 0.f;

    const float* inb = in + (size_t)bb * CDIM * HW;

    for (int ic0 = 0; ic0 < CDIM; ic0 += 32) {
        // load X chunk: 32 ic x 256 px, float4-vectorized
#pragma unroll
        for (int j = 0; j < 8; j++) {
            int idx = j * 256 + t;
            int ic = idx >> 6, px4 = idx & 63;
            float4 v = *reinterpret_cast<const float4*>(&inb[(ic0 + ic) * HW + p0 + px4 * 4]);
            v.x = f2tf(v.x); v.y = f2tf(v.y); v.z = f2tf(v.z); v.w = f2tf(v.w);
            *reinterpret_cast<float4*>(&sX[ic * XSTR + px4 * 4]) = v;
        }
        // load W chunk: 64 oc x 32 ic
#pragma unroll
        for (int j = 0; j < 2; j++) {
            int idx = j * 256 + t;
            int oc = idx >> 3, icq = idx & 7;
            float4 v = *reinterpret_cast<const float4*>(&w[(size_t)(ocT * 64 + oc) * CDIM + ic0 + icq * 4]);
            v.x = f2tf(v.x); v.y = f2tf(v.y); v.z = f2tf(v.z); v.w = f2tf(v.w);
            *reinterpret_cast<float4*>(&sW[oc * WSTR + icq * 4]) = v;
        }
        __syncthreads();

#pragma unroll
        for (int ks = 0; ks < 4; ks++) {
            int kk = ks * 8;
            uint32_t a[2][4];
#pragma unroll
            for (int i = 0; i < 2; i++) {
                int row = wm * 32 + i * 16 + g;
                a[i][0] = __float_as_uint(sW[row * WSTR + kk + tg]);
                a[i][1] = __float_as_uint(sW[(row + 8) * WSTR + kk + tg]);
                a[i][2] = __float_as_uint(sW[row * WSTR + kk + tg + 4]);
                a[i][3] = __float_as_uint(sW[(row + 8) * WSTR + kk + tg + 4]);
            }
#pragma unroll
            for (int j = 0; j < 8; j++) {
                int px = wn * 64 + j * 8 + g;
                uint32_t b0 = __float_as_uint(sX[(kk + tg) * XSTR + px]);
                uint32_t b1 = __float_as_uint(sX[(kk + tg + 4) * XSTR + px]);
                mma_tf32(acc[0][j], a[0][0], a[0][1], a[0][2], a[0][3], b0, b1);
                mma_tf32(acc[1][j], a[1][0], a[1][1], a[1][2], a[1][3], b0, b1);
            }
        }
        __syncthreads();
    }

    // epilogue + optional BN
#pragma unroll
    for (int i = 0; i < 2; i++) {
        int oc_lo = ocT * 64 + wm * 32 + i * 16 + g;
        int oc_hi = oc_lo + 8;
        float sc0 = 1.f, sh0 = 0.f, sc1 = 1.f, sh1 = 0.f;
        if (bng) {
            sc0 = bng[oc_lo] * rsqrtf(bnv[oc_lo] + EPS); sh0 = bnb[oc_lo] - bnm[oc_lo] * sc0;
            sc1 = bng[oc_hi] * rsqrtf(bnv[oc_hi] + EPS); sh1 = bnb[oc_hi] - bnm[oc_hi] * sc1;
        }
#pragma unroll
        for (int j = 0; j < 8; j++) {
            int px = p0 + wn * 64 + j * 8 + 2 * tg;
            float* o0 = &out[((size_t)bb * OC + oc_lo) * HW + px];
            float* o1 = &out[((size_t)bb * OC + oc_hi) * HW + px];
            o0[0] = acc[i][j][0] * sc0 + sh0;
            o0[1] = acc[i][j][1] * sc0 + sh0;
            o1[0] = acc[i][j][2] * sc1 + sh1;
            o1[1] = acc[i][j][3] * sc1 + sh1;
        }
    }
}

// ---------------- KxK conv (256->256) via tf32 tensor cores ------------------
// Block: 64 oc x (8h x 32w) px, 256 threads, warp tile 32 oc x (2h x 32w).
// ic chunks of 8 (one mma k-step per tap). All KS^2 weight taps in SMEM.
template<int KS, bool ADD_HIGH>
__global__ __launch_bounds__(256, 2)
void conv_mma(const float* __restrict__ in, const float* __restrict__ wgt,
              const float* __restrict__ bng, const float* __restrict__ bnb,
              const float* __restrict__ bnm, const float* __restrict__ bnv,
              float* __restrict__ out,
              const float* __restrict__ khbuf, float* __restrict__ out2)
{
    constexpr int PAD = KS / 2;
    constexpr int PH = 8 + KS - 1;
    constexpr int PW = 32 + KS - 1;
    // padded row stride so that PH*PWS % 32 == 8 (conflict-free B loads)
    constexpr int PWS = (KS == 5) ? 38 : 36;
    constexpr int KKS = KS * KS;

    extern __shared__ float smem[];
    float* sP = smem;                       // [8][PH][PWS]
    float* sW = smem + 8 * PH * PWS;        // [KKS][64][8]

    const int w0 = blockIdx.x * 32;
    const int h0 = blockIdx.y * 8;
    const int bb  = blockIdx.z >> 2;
    const int ocT = blockIdx.z & 3;
    const int t = threadIdx.x;
    const int warp = t >> 5, lane = t & 31;
    const int g = lane >> 2, tg = lane & 3;
    const int wm = warp >> 2;               // oc base wm*32
    const int wn = warp & 3;                // h rows [wn*2, wn*2+2)

    float acc[2][8][4];
#pragma unroll
    for (int i = 0; i < 2; i++)
#pragma unroll
        for (int j = 0; j < 8; j++)
#pragma unroll
            for (int c = 0; c < 4; c++) acc[i][j][c] = 0.f;

    for (int ic0 = 0; ic0 < CDIM; ic0 += 8) {
        // input patch: 8 ic x PH x PW (zero padded at borders)
        for (int e = t; e < 8 * PH * PW; e += 256) {
            int ic = e / (PH * PW), rem = e % (PH * PW);
            int row = rem / PW, cc = rem % PW;
            int h = h0 + row - PAD, w = w0 + cc - PAD;
            float v = 0.f;
            if (h >= 0 && h < HDIM && w >= 0 && w < WDIM)
                v = f2tf(in[((size_t)(bb * CDIM + ic0 + ic) * HDIM + h) * WDIM + w]);
            sP[ic * PH * PWS + row * PWS + cc] = v;
        }
        // weights: all taps, 64 oc x 8 ic
        for (int e = t; e < 64 * 8 * KKS; e += 256) {
            int oc = e / (8 * KKS), rem = e % (8 * KKS);
            int ic = rem / KKS, tap = rem % KKS;
            sW[tap * 512 + oc * 8 + ic] =
                f2tf(wgt[((size_t)(ocT * 64 + oc) * CDIM + ic0 + ic) * KKS + tap]);
        }
        __syncthreads();

#pragma unroll
        for (int ky = 0; ky < KS; ky++)
#pragma unroll
            for (int kx = 0; kx < KS; kx++) {
                const int tap = ky * KS + kx;
                uint32_t a[2][4];
#pragma unroll
                for (int i = 0; i < 2; i++) {
                    int row = wm * 32 + i * 16 + g;
                    a[i][0] = __float_as_uint(sW[tap * 512 + row * 8 + tg]);
                    a[i][1] = __float_as_uint(sW[tap * 512 + (row + 8) * 8 + tg]);
                    a[i][2] = __float_as_uint(sW[tap * 512 + row * 8 + tg + 4]);
                    a[i][3] = __float_as_uint(sW[tap * 512 + (row + 8) * 8 + tg + 4]);
                }
#pragma unroll
                for (int j = 0; j < 8; j++) {
                    int hr = wn * 2 + (j >> 2) + ky;      // patch row
                    int wc = (j & 3) * 8 + kx + g;        // patch col
                    uint32_t b0 = __float_as_uint(sP[tg * PH * PWS + hr * PWS + wc]);
                    uint32_t b1 = __float_as_uint(sP[(tg + 4) * PH * PWS + hr * PWS + wc]);
                    mma_tf32(acc[0][j], a[0][0], a[0][1], a[0][2], a[0][3], b0, b1);
                    mma_tf32(acc[1][j], a[1][0], a[1][1], a[1][2], a[1][3], b0, b1);
                }
            }
        __syncthreads();
    }

#pragma unroll
    for (int i = 0; i < 2; i++) {
        int oc_lo = ocT * 64 + wm * 32 + i * 16 + g;
        int oc_hi = oc_lo + 8;
        float sc0 = bng[oc_lo] * rsqrtf(bnv[oc_lo] + EPS);
        float sh0 = bnb[oc_lo] - bnm[oc_lo] * sc0;
        float sc1 = bng[oc_hi] * rsqrtf(bnv[oc_hi] + EPS);
        float sh1 = bnb[oc_hi] - bnm[oc_hi] * sc1;
#pragma unroll
        for (int j = 0; j < 8; j++) {
            int h = h0 + wn * 2 + (j >> 2);
            int w = w0 + (j & 3) * 8 + 2 * tg;
            size_t i0 = ((size_t)(bb * CDIM + oc_lo) * HDIM + h) * WDIM + w;
            size_t i1 = ((size_t)(bb * CDIM + oc_hi) * HDIM + h) * WDIM + w;
            float v00 = acc[i][j][0] * sc0 + sh0;
            float v01 = acc[i][j][1] * sc0 + sh0;
            float v10 = acc[i][j][2] * sc1 + sh1;
            float v11 = acc[i][j][3] * sc1 + sh1;
            out[i0] = v00; out[i0 + 1] = v01;
            out[i1] = v10; out[i1 + 1] = v11;
            if (ADD_HIGH) {
                out2[i0] = v00 + khbuf[i0]; out2[i0 + 1] = v01 + khbuf[i0 + 1];
                out2[i1] = v10 + khbuf[i1]; out2[i1 + 1] = v11 + khbuf[i1 + 1];
            }
        }
    }
}

// ---------------- window attention (unchanged) -------------------------------
__global__ __launch_bounds__(64)
void attn_kernel(const float* __restrict__ qkv, const float* __restrict__ qh,
                 const float* __restrict__ kh, const float* __restrict__ rel_table,
                 float* __restrict__ low)
{
    __shared__ float sK[64 * 16];
    __shared__ float sV[64 * 16];
    __shared__ float sKH[64 * 16];
    __shared__ float sRT[225];

    const int wi = blockIdx.x;
    const int head = blockIdx.y;
    const int bb = blockIdx.z;
    const int hh = wi >> 4, ww = wi & 15;
    const int n = threadIdx.x;
    const int rn = n >> 3, cn = n & 7;
    const int hq = hh * 8 + rn, wq = ww * 8 + cn;

    float qr[16], qhr[16];
#pragma unroll
    for (int d = 0; d < 16; d++) {
        int ch = head * 16 + d;
        sK [n * 16 + d] = qkv[((size_t)(bb * 768 + 256 + ch) * HDIM + hq) * WDIM + wq];
        sV [n * 16 + d] = qkv[((size_t)(bb * 768 + 512 + ch) * HDIM + hq) * WDIM + wq];
        sKH[n * 16 + d] = kh [((size_t)(bb * CDIM + ch) * HDIM + hq) * WDIM + wq];
        qr [d] = qkv[((size_t)(bb * 768 + ch) * HDIM + hq) * WDIM + wq];
        qhr[d] = qh [((size_t)(bb * CDIM + ch) * HDIM + hq) * WDIM + wq];
    }
    for (int i = n; i < 225; i += 64) sRT[i] = rel_table[i * NHEAD + head];
    __syncthreads();

    const float scale = 0.25f;
    float dots[64];
#pragma unroll
    for (int m = 0; m < 64; m++) {
        float d0 = 0.f;
#pragma unroll
        for (int d = 0; d < 16; d++)
            d0 += qr[d] * sK[m * 16 + d] + qhr[d] * sKH[m * 16 + d];
        int rm = m >> 3, cm = m & 7;
        int idx = (rn - rm + 7) * 15 + (cn - cm + 7);
        dots[m] = d0 * scale + sRT[idx];
    }
    float mx = -1e30f;
#pragma unroll
    for (int m = 0; m < 64; m++) mx = fmaxf(mx, dots[m]);
    float sum = 0.f;
#pragma unroll
    for (int m = 0; m < 64; m++) { float e = __expf(dots[m] - mx); sum += e; dots[m] = e; }
    float inv = 1.f / sum;
    float o[16];
#pragma unroll
    for (int d = 0; d < 16; d++) o[d] = 0.f;
#pragma unroll
    for (int m = 0; m < 64; m++) {
        float p = dots[m] * inv;
#pragma unroll
        for (int d = 0; d < 16; d++) o[d] += p * sV[m * 16 + d];
    }
#pragma unroll
    for (int d = 0; d < 16; d++)
        low[((size_t)(bb * CDIM + head * 16 + d) * HDIM + hq) * WDIM + wq] = o[d];
}

// ---------------- channel mean/max pool --------------------------------------
__global__ void pool_kernel(const float* __restrict__ low, const float* __restrict__ high,
                            float* __restrict__ pool)
{
    int p = blockIdx.x * 256 + threadIdx.x;
    int bb = blockIdx.y;
    const float* lb = low  + (size_t)bb * CDIM * HW;
    const float* hb = high + (size_t)bb * CDIM * HW;
    float s = 0.f, mx = -1e30f;
    for (int c = 0; c < CDIM; c++) {
        float v = lb[c * HW + p] + hb[c * HW + p];
        s += v; mx = fmaxf(mx, v);
    }
    pool[(bb * 2 + 0) * HW + p] = s * (1.f / 256.f);
    pool[(bb * 2 + 1) * HW + p] = mx;
}

// ---------------- hybrid 7x7 conv (2->2) + sigmoid ---------------------------
__global__ void hybrid_kernel(const float* __restrict__ pool, const float* __restrict__ hw,
                              const float* __restrict__ hb, float* __restrict__ sig)
{
    __shared__ float sw[196];
    __shared__ float sb[2];
    int t = threadIdx.x;
    if (t < 196) sw[t] = hw[t];
    if (t < 2) sb[t] = hb[t];
    __syncthreads();
    int p = blockIdx.x * 256 + t;
    int bb = blockIdx.y;
    int h = p >> 7, w = p & 127;
#pragma unroll
    for (int oc = 0; oc < 2; oc++) {
        float acc = sb[oc];
#pragma unroll
        for (int ic = 0; ic < 2; ic++)
            for (int ky = 0; ky < 7; ky++) {
                int hy = h + ky - 3;
                if (hy < 0 || hy >= HDIM) continue;
                for (int kx = 0; kx < 7; kx++) {
                    int wx = w + kx - 3;
                    if (wx < 0 || wx >= WDIM) continue;
                    acc += pool[(bb * 2 + ic) * HW + hy * WDIM + wx] * sw[((oc * 2 + ic) * 7 + ky) * 7 + kx];
                }
            }
        sig[(bb * 2 + oc) * HW + p] = 1.f / (1.f + __expf(-acc));
    }
}

// ---------------- mix --------------------------------------------------------
__global__ void mix_kernel(const float* __restrict__ low, const float* __restrict__ high,
                           const float* __restrict__ sig, float* __restrict__ out)
{
    int idx = blockIdx.x * 256 + threadIdx.x;
    int p = idx & (HW - 1);
    int bb = idx >> 22;
    float s0 = sig[(bb * 2 + 0) * HW + p];
    float s1 = sig[(bb * 2 + 1) * HW + p];
    out[idx] = low[idx] * s0 + high[idx] * s1;
}

// ---------------- depthwise 7x7 + BN -----------------------------------------
__global__ void dw_kernel(const float* __restrict__ in, const float* __restrict__ w,
                          const float* __restrict__ bng, const float* __restrict__ bnb,
                          const float* __restrict__ bnm, const float* __restrict__ bnv,
                          float* __restrict__ out)
{
    __shared__ float sT[14 * 38];
    __shared__ float sWc[49];
    const int w0 = blockIdx.x * 32;
    const int h0 = blockIdx.y * 8;
    const int bc = blockIdx.z;
    const int c = bc & 255;
    const int tx = threadIdx.x, ty = threadIdx.y;
    const int t = ty * 32 + tx;
    if (t < 49) sWc[t] = w[c * 49 + t];
    const float* inb = in + (size_t)bc * HW;
    for (int e = t; e < 14 * 38; e += 256) {
        int row = e / 38, cc = e % 38;
        int h = h0 + row - 3, ww = w0 + cc - 3;
        float v = 0.f;
        if (h >= 0 && h < HDIM && ww >= 0 && ww < WDIM) v = inb[h * WDIM + ww];
        sT[e] = v;
    }
    __syncthreads();
    float acc = 0.f;
#pragma unroll
    for (int ky = 0; ky < 7; ky++)
#pragma unroll
        for (int kx = 0; kx < 7; kx++)
            acc += sT[(ty + ky) * 38 + tx + kx] * sWc[ky * 7 + kx];
    float sc = bng[c] * rsqrtf(bnv[c] + EPS);
    float sh = bnb[c] - bnm[c] * sc;
    out[(size_t)bc * HW + (h0 + ty) * WDIM + w0 + tx] = acc * sc + sh;
}

// ---------------- launch ------------------------------------------------------
extern "C" void kernel_launch(void* const* d_in, const int* in_sizes, int n_in,
                              void* d_out, int out_size)
{
    const float* x        = (const float*)d_in[0];
    const float* qkv_w    = (const float*)d_in[1];
    const float* local1_w = (const float*)d_in[2];
    const float* l1g = (const float*)d_in[3];
    const float* l1b = (const float*)d_in[4];
    const float* l1m = (const float*)d_in[5];
    const float* l1v = (const float*)d_in[6];
    const float* local2_w = (const float*)d_in[7];
    const float* l2g = (const float*)d_in[8];
    const float* l2b = (const float*)d_in[9];
    const float* l2m = (const float*)d_in[10];
    const float* l2v = (const float*)d_in[11];
    const float* rel_table = (const float*)d_in[12];
    const float* hybrid_w  = (const float*)d_in[13];
    const float* hybrid_b  = (const float*)d_in[14];
    const float* smooth_w  = (const float*)d_in[15];
    const float* smg = (const float*)d_in[16];
    const float* smb = (const float*)d_in[17];
    const float* smm = (const float*)d_in[18];
    const float* smv = (const float*)d_in[19];
    const float* proj_dw_w = (const float*)d_in[20];
    const float* prg = (const float*)d_in[21];
    const float* prb = (const float*)d_in[22];
    const float* prm = (const float*)d_in[23];
    const float* prv = (const float*)d_in[24];
    const float* proj_pw_w = (const float*)d_in[25];

    float *p_qh, *p_kh, *p_high, *p_qkv, *p_low, *p_mix, *p_sm, *p_dw, *p_pool, *p_sig;
    cudaGetSymbolAddress((void**)&p_qh,   g_qh);
    cudaGetSymbolAddress((void**)&p_kh,   g_kh);
    cudaGetSymbolAddress((void**)&p_high, g_high);
    cudaGetSymbolAddress((void**)&p_qkv,  g_qkv);
    cudaGetSymbolAddress((void**)&p_low,  g_low);
    cudaGetSymbolAddress((void**)&p_mix,  g_mix);
    cudaGetSymbolAddress((void**)&p_sm,   g_sm);
    cudaGetSymbolAddress((void**)&p_dw,   g_dw);
    cudaGetSymbolAddress((void**)&p_pool, g_pool);
    cudaGetSymbolAddress((void**)&p_sig,  g_sig);

    // dynamic smem sizes for the conv kernels
    const int smem3 = (8 * 10 * 36 + 9  * 64 * 8) * 4;   // 29952 B
    const int smem5 = (8 * 12 * 38 + 25 * 64 * 8) * 4;   // 65792 B
    static bool attr_done = false;
    if (!attr_done) {
        cudaFuncSetAttribute(conv_mma<5, false>, cudaFuncAttributeMaxDynamicSharedMemorySize, smem5);
        cudaFuncSetAttribute(conv_mma<3, true>,  cudaFuncAttributeMaxDynamicSharedMemorySize, smem3);
        attr_done = true;
    }

    // qkv = 1x1 conv (768 oc)
    gemm1x1_mma<<<dim3(64, 12, 4), 256>>>(x, qkv_w, nullptr, nullptr, nullptr, nullptr, p_qkv, 768);
    // k_h = BN(1x1 conv)
    gemm1x1_mma<<<dim3(64, 4, 4), 256>>>(x, local2_w, l2g, l2b, l2m, l2v, p_kh, 256);
    // q_h = BN(3x3 conv); also high = q_h + k_h
    conv_mma<3, true><<<dim3(4, 16, 16), 256, smem3>>>(x, local1_w, l1g, l1b, l1m, l1v,
                                                       p_qh, p_kh, p_high);
    // window attention -> low_freq
    attn_kernel<<<dim3(256, 16, 4), 64>>>(p_qkv, p_qh, p_kh, rel_table, p_low);
    // channel pool
    pool_kernel<<<dim3(64, 4), 256>>>(p_low, p_high, p_pool);
    // hybrid gate
    hybrid_kernel<<<dim3(64, 4), 256>>>(p_pool, hybrid_w, hybrid_b, p_sig);
    // mix
    mix_kernel<<<dim3(BDIM * CDIM * HW / 256), 256>>>(p_low, p_high, p_sig, p_mix);
    // smooth 5x5 + BN
    conv_mma<5, false><<<dim3(4, 16, 16), 256, smem5>>>(p_mix, smooth_w, smg, smb, smm, smv,
                                                        p_sm, nullptr, nullptr);
    // depthwise 7x7 + BN
    dw_kernel<<<dim3(4, 16, 1024), dim3(32, 8)>>>(p_sm, proj_dw_w, prg, prb, prm, prv, p_dw);
    // final pointwise 1x1 -> d_out
    gemm1x1_mma<<<dim3(64, 4, 4), 256>>>(p_dw, proj_pw_w, nullptr, nullptr, nullptr, nullptr,
                                         (float*)d_out, 256);
}

// round 3
// speedup vs baseline: 3.9189x; 1.5065x over previous
#include <cuda_runtime.h>
#include <math.h>
#include <stdint.h>

#define HDIM 128
#define WDIM 128
#define HW (HDIM*WDIM)
#define CDIM 256
#define BDIM 4
#define NHEAD 16
#define EPS 1e-5f

// ---------------- scratch ----------------------------------------------------
__device__ float g_qh  [BDIM*CDIM*HW];
__device__ float g_kh  [BDIM*CDIM*HW];
__device__ float g_high[BDIM*CDIM*HW];
__device__ float g_qkv [BDIM*3*CDIM*HW];
__device__ float g_low [BDIM*CDIM*HW];
__device__ float g_mix [BDIM*CDIM*HW];
__device__ float g_sm  [BDIM*CDIM*HW];
__device__ float g_dw  [BDIM*CDIM*HW];
__device__ float g_pool[BDIM*2*HW];
__device__ float g_sig [BDIM*2*HW];
// pre-rounded / transformed operands
__device__ float g_xr  [BDIM*CDIM*HW];
__device__ float g_w5t [CDIM*CDIM*25];
__device__ float g_w3t [CDIM*CDIM*9];
__device__ float g_wq  [3*CDIM*CDIM];
__device__ float g_w2  [CDIM*CDIM];
__device__ float g_wp  [CDIM*CDIM];

// ---------------- tf32 / cp.async helpers ------------------------------------
__device__ __forceinline__ float f2tf(float f) {
    uint32_t u;
    asm("cvt.rna.tf32.f32 %0, %1;" : "=r"(u) : "f"(f));
    return __uint_as_float(u);
}

__device__ __forceinline__ void cp16(float* dst, const float* src) {
    uint32_t d = (uint32_t)__cvta_generic_to_shared(dst);
    asm volatile("cp.async.cg.shared.global [%0], [%1], 16;" :: "r"(d), "l"(src));
}
__device__ __forceinline__ void cp4z(float* dst, const float* src, bool pred) {
    uint32_t d = (uint32_t)__cvta_generic_to_shared(dst);
    int sz = pred ? 4 : 0;
    asm volatile("cp.async.ca.shared.global [%0], [%1], 4, %2;" :: "r"(d), "l"(src), "r"(sz));
}
__device__ __forceinline__ void cp_commit() {
    asm volatile("cp.async.commit_group;");
}
__device__ __forceinline__ void cp_wait1() {
    asm volatile("cp.async.wait_group 1;");
}

__device__ __forceinline__ void mma_tf32(float* d, uint32_t a0, uint32_t a1,
                                         uint32_t a2, uint32_t a3,
                                         uint32_t b0, uint32_t b1) {
    asm volatile(
        "mma.sync.aligned.m16n8k8.row.col.f32.tf32.tf32.f32 "
        "{%0,%1,%2,%3}, {%4,%5,%6,%7}, {%8,%9}, {%0,%1,%2,%3};"
        : "+f"(d[0]), "+f"(d[1]), "+f"(d[2]), "+f"(d[3])
        : "r"(a0), "r"(a1), "r"(a2), "r"(a3), "r"(b0), "r"(b1));
}

// ---------------- pre-pass kernels -------------------------------------------
__global__ void round_copy(const float* __restrict__ in, float* __restrict__ out, int n)
{
    int i = blockIdx.x * 256 + threadIdx.x;
    if (i < n) out[i] = f2tf(in[i]);
}

// transform KxK weights into per-chunk smem layout:
// dst[((ocT*32+ics)*KKS + tap)*512 + oc*8 + ic] = wgt[((ocT*64+oc)*256 + ics*8+ic)*KKS + tap]
template<int KKS>
__global__ void wtransform(const float* __restrict__ wgt, float* __restrict__ dst)
{
    int tid = blockIdx.x * 256 + threadIdx.x;
    int total = 4 * 32 * KKS * 512;
    if (tid >= total) return;
    int ic  = tid & 7;
    int oc  = (tid >> 3) & 63;
    int tap = (tid >> 9) % KKS;
    int ics = (tid / (512 * KKS)) & 31;
    int ocT = tid / (512 * KKS * 32);
    dst[tid] = f2tf(wgt[((size_t)((ocT * 64 + oc) * 256 + ics * 8 + ic)) * KKS + tap]);
}

// ---------------- 1x1 conv as tf32 GEMM, cp.async double-buffered ------------
#define XSTR 264
#define WSTR 36
#define GEM_XF (32*XSTR)    // 8448 floats
#define GEM_WF (64*WSTR)    // 2304 floats
#define GEM_STG (GEM_XF+GEM_WF)

__global__ __launch_bounds__(256, 2)
void gemm1x1_mma(const float* __restrict__ in, const float* __restrict__ w,
                 const float* __restrict__ bng, const float* __restrict__ bnb,
                 const float* __restrict__ bnm, const float* __restrict__ bnv,
                 float* __restrict__ out, int OC)
{
    extern __shared__ float smem[];

    const int bb  = blockIdx.z;
    const int ocT = blockIdx.y;
    const int p0  = blockIdx.x * 256;
    const int t   = threadIdx.x;
    const int warp = t >> 5, lane = t & 31;
    const int g = lane >> 2, tg = lane & 3;
    const int wm = warp >> 2;
    const int wn = warp & 3;

    const float* inb = in + (size_t)bb * CDIM * HW;

    // load lambda: stage s, chunk ic0
    auto load = [&](int s, int ic0) {
        float* sX = smem + s * GEM_STG;
        float* sW = sX + GEM_XF;
#pragma unroll
        for (int j = 0; j < 8; j++) {
            int idx = j * 256 + t;
            int ic = idx >> 6, px4 = idx & 63;
            cp16(&sX[ic * XSTR + px4 * 4], &inb[(ic0 + ic) * HW + p0 + px4 * 4]);
        }
#pragma unroll
        for (int j = 0; j < 2; j++) {
            int idx = j * 256 + t;
            int oc = idx >> 3, icq = idx & 7;
            cp16(&sW[oc * WSTR + icq * 4], &w[(size_t)(ocT * 64 + oc) * CDIM + ic0 + icq * 4]);
        }
    };

    float acc[2][8][4];
#pragma unroll
    for (int i = 0; i < 2; i++)
#pragma unroll
        for (int j = 0; j < 8; j++)
#pragma unroll
            for (int c = 0; c < 4; c++) acc[i][j][c] = 0.f;

    load(0, 0);
    cp_commit();

    for (int ic0 = 0; ic0 < CDIM; ic0 += 32) {
        int cur = (ic0 >> 5) & 1;
        if (ic0 + 32 < CDIM) load(cur ^ 1, ic0 + 32);
        cp_commit();
        cp_wait1();
        __syncthreads();

        float* sX = smem + cur * GEM_STG;
        float* sW = sX + GEM_XF;
#pragma unroll
        for (int ks = 0; ks < 4; ks++) {
            int kk = ks * 8;
            uint32_t a[2][4];
#pragma unroll
            for (int i = 0; i < 2; i++) {
                int row = wm * 32 + i * 16 + g;
                a[i][0] = __float_as_uint(sW[row * WSTR + kk + tg]);
                a[i][1] = __float_as_uint(sW[(row + 8) * WSTR + kk + tg]);
                a[i][2] = __float_as_uint(sW[row * WSTR + kk + tg + 4]);
                a[i][3] = __float_as_uint(sW[(row + 8) * WSTR + kk + tg + 4]);
            }
#pragma unroll
            for (int j = 0; j < 8; j++) {
                int px = wn * 64 + j * 8 + g;
                uint32_t b0 = __float_as_uint(sX[(kk + tg) * XSTR + px]);
                uint32_t b1 = __float_as_uint(sX[(kk + tg + 4) * XSTR + px]);
                mma_tf32(acc[0][j], a[0][0], a[0][1], a[0][2], a[0][3], b0, b1);
                mma_tf32(acc[1][j], a[1][0], a[1][1], a[1][2], a[1][3], b0, b1);
            }
        }
        __syncthreads();
    }

#pragma unroll
    for (int i = 0; i < 2; i++) {
        int oc_lo = ocT * 64 + wm * 32 + i * 16 + g;
        int oc_hi = oc_lo + 8;
        float sc0 = 1.f, sh0 = 0.f, sc1 = 1.f, sh1 = 0.f;
        if (bng) {
            sc0 = bng[oc_lo] * rsqrtf(bnv[oc_lo] + EPS); sh0 = bnb[oc_lo] - bnm[oc_lo] * sc0;
            sc1 = bng[oc_hi] * rsqrtf(bnv[oc_hi] + EPS); sh1 = bnb[oc_hi] - bnm[oc_hi] * sc1;
        }
#pragma unroll
        for (int j = 0; j < 8; j++) {
            int px = p0 + wn * 64 + j * 8 + 2 * tg;
            float* o0 = &out[((size_t)bb * OC + oc_lo) * HW + px];
            float* o1 = &out[((size_t)bb * OC + oc_hi) * HW + px];
            o0[0] = acc[i][j][0] * sc0 + sh0;
            o0[1] = acc[i][j][1] * sc0 + sh0;
            o1[0] = acc[i][j][2] * sc1 + sh1;
            o1[1] = acc[i][j][3] * sc1 + sh1;
        }
    }
}

// ---------------- KxK conv via tf32 MMA, cp.async double-buffered ------------
// weights pre-transformed: [(ocT*32+ics)*KKS + tap][64oc*8ic] contiguous
template<int KS, bool ADD_HIGH>
__global__ __launch_bounds__(256, (KS == 3 ? 2 : 1))
void conv_mma(const float* __restrict__ in, const float* __restrict__ wt,
              const float* __restrict__ bng, const float* __restrict__ bnb,
              const float* __restrict__ bnm, const float* __restrict__ bnv,
              float* __restrict__ out,
              const float* __restrict__ khbuf, float* __restrict__ out2)
{
    constexpr int PAD = KS / 2;
    constexpr int PH = 8 + KS - 1;
    constexpr int PW = 32 + KS - 1;
    constexpr int PWS = PW + 2;               // 38 / 36 ; PH*PWS % 32 == 8
    constexpr int KKS = KS * KS;
    constexpr int PATCHF = 8 * PH * PWS;
    constexpr int WGTF = KKS * 512;
    constexpr int STG = PATCHF + WGTF;

    extern __shared__ float smem[];

    const int w0 = blockIdx.x * 32;
    const int h0 = blockIdx.y * 8;
    const int bb  = blockIdx.z >> 2;
    const int ocT = blockIdx.z & 3;
    const int t = threadIdx.x;
    const int warp = t >> 5, lane = t & 31;
    const int g = lane >> 2, tg = lane & 3;
    const int wm = warp >> 2;
    const int wn = warp & 3;

    auto load = [&](int s, int ic0) {
        float* sP = smem + s * STG;
        float* sW = sP + PATCHF;
        // patch: 8 ic x PH x PW, 4B cp.async with zero-fill for OOB
        for (int e = t; e < 8 * PH * PW; e += 256) {
            int ic = e / (PH * PW), rem = e % (PH * PW);
            int row = rem / PW, cc = rem % PW;
            int h = h0 + row - PAD, w = w0 + cc - PAD;
            bool ok = ((unsigned)h < HDIM) && ((unsigned)w < WDIM);
            const float* src = in + ((size_t)(bb * CDIM + ic0 + ic) * HDIM + (ok ? h : 0)) * WDIM + (ok ? w : 0);
            cp4z(&sP[ic * PH * PWS + row * PWS + cc], src, ok);
        }
        // weights: contiguous chunk, 16B cp.async
        const float* base = wt + (size_t)(ocT * 32 + (ic0 >> 3)) * WGTF;
        for (int e = t * 4; e < WGTF; e += 1024)
            cp16(&sW[e], &base[e]);
    };

    float acc[2][8][4];
#pragma unroll
    for (int i = 0; i < 2; i++)
#pragma unroll
        for (int j = 0; j < 8; j++)
#pragma unroll
            for (int c = 0; c < 4; c++) acc[i][j][c] = 0.f;

    load(0, 0);
    cp_commit();

    for (int ic0 = 0; ic0 < CDIM; ic0 += 8) {
        int cur = (ic0 >> 3) & 1;
        if (ic0 + 8 < CDIM) load(cur ^ 1, ic0 + 8);
        cp_commit();
        cp_wait1();
        __syncthreads();

        float* sP = smem + cur * STG;
        float* sW = sP + PATCHF;
#pragma unroll
        for (int ky = 0; ky < KS; ky++)
#pragma unroll
            for (int kx = 0; kx < KS; kx++) {
                const int tap = ky * KS + kx;
                uint32_t a[2][4];
#pragma unroll
                for (int i = 0; i < 2; i++) {
                    int row = wm * 32 + i * 16 + g;
                    a[i][0] = __float_as_uint(sW[tap * 512 + row * 8 + tg]);
                    a[i][1] = __float_as_uint(sW[tap * 512 + (row + 8) * 8 + tg]);
                    a[i][2] = __float_as_uint(sW[tap * 512 + row * 8 + tg + 4]);
                    a[i][3] = __float_as_uint(sW[tap * 512 + (row + 8) * 8 + tg + 4]);
                }
#pragma unroll
                for (int j = 0; j < 8; j++) {
                    int hr = wn * 2 + (j >> 2) + ky;
                    int wc = (j & 3) * 8 + kx + g;
                    uint32_t b0 = __float_as_uint(sP[tg * PH * PWS + hr * PWS + wc]);
                    uint32_t b1 = __float_as_uint(sP[(tg + 4) * PH * PWS + hr * PWS + wc]);
                    mma_tf32(acc[0][j], a[0][0], a[0][1], a[0][2], a[0][3], b0, b1);
                    mma_tf32(acc[1][j], a[1][0], a[1][1], a[1][2], a[1][3], b0, b1);
                }
            }
        __syncthreads();
    }

#pragma unroll
    for (int i = 0; i < 2; i++) {
        int oc_lo = ocT * 64 + wm * 32 + i * 16 + g;
        int oc_hi = oc_lo + 8;
        float sc0 = bng[oc_lo] * rsqrtf(bnv[oc_lo] + EPS);
        float sh0 = bnb[oc_lo] - bnm[oc_lo] * sc0;
        float sc1 = bng[oc_hi] * rsqrtf(bnv[oc_hi] + EPS);
        float sh1 = bnb[oc_hi] - bnm[oc_hi] * sc1;
#pragma unroll
        for (int j = 0; j < 8; j++) {
            int h = h0 + wn * 2 + (j >> 2);
            int w = w0 + (j & 3) * 8 + 2 * tg;
            size_t i0 = ((size_t)(bb * CDIM + oc_lo) * HDIM + h) * WDIM + w;
            size_t i1 = ((size_t)(bb * CDIM + oc_hi) * HDIM + h) * WDIM + w;
            float v00 = acc[i][j][0] * sc0 + sh0;
            float v01 = acc[i][j][1] * sc0 + sh0;
            float v10 = acc[i][j][2] * sc1 + sh1;
            float v11 = acc[i][j][3] * sc1 + sh1;
            out[i0] = v00; out[i0 + 1] = v01;
            out[i1] = v10; out[i1 + 1] = v11;
            if (ADD_HIGH) {
                out2[i0] = v00 + khbuf[i0]; out2[i0 + 1] = v01 + khbuf[i0 + 1];
                out2[i1] = v10 + khbuf[i1]; out2[i1 + 1] = v11 + khbuf[i1 + 1];
            }
        }
    }
}

// ---------------- window attention -------------------------------------------
__global__ __launch_bounds__(64)
void attn_kernel(const float* __restrict__ qkv, const float* __restrict__ qh,
                 const float* __restrict__ kh, const float* __restrict__ rel_table,
                 float* __restrict__ low)
{
    __shared__ float sK[64 * 16];
    __shared__ float sV[64 * 16];
    __shared__ float sKH[64 * 16];
    __shared__ float sRT[225];

    const int wi = blockIdx.x;
    const int head = blockIdx.y;
    const int bb = blockIdx.z;
    const int hh = wi >> 4, ww = wi & 15;
    const int n = threadIdx.x;
    const int rn = n >> 3, cn = n & 7;
    const int hq = hh * 8 + rn, wq = ww * 8 + cn;

    float qr[16], qhr[16];
#pragma unroll
    for (int d = 0; d < 16; d++) {
        int ch = head * 16 + d;
        sK [n * 16 + d] = qkv[((size_t)(bb * 768 + 256 + ch) * HDIM + hq) * WDIM + wq];
        sV [n * 16 + d] = qkv[((size_t)(bb * 768 + 512 + ch) * HDIM + hq) * WDIM + wq];
        sKH[n * 16 + d] = kh [((size_t)(bb * CDIM + ch) * HDIM + hq) * WDIM + wq];
        qr [d] = qkv[((size_t)(bb * 768 + ch) * HDIM + hq) * WDIM + wq];
        qhr[d] = qh [((size_t)(bb * CDIM + ch) * HDIM + hq) * WDIM + wq];
    }
    for (int i = n; i < 225; i += 64) sRT[i] = rel_table[i * NHEAD + head];
    __syncthreads();

    const float scale = 0.25f;
    float dots[64];
#pragma unroll
    for (int m = 0; m < 64; m++) {
        float d0 = 0.f;
#pragma unroll
        for (int d = 0; d < 16; d++)
            d0 += qr[d] * sK[m * 16 + d] + qhr[d] * sKH[m * 16 + d];
        int rm = m >> 3, cm = m & 7;
        int idx = (rn - rm + 7) * 15 + (cn - cm + 7);
        dots[m] = d0 * scale + sRT[idx];
    }
    float mx = -1e30f;
#pragma unroll
    for (int m = 0; m < 64; m++) mx = fmaxf(mx, dots[m]);
    float sum = 0.f;
#pragma unroll
    for (int m = 0; m < 64; m++) { float e = __expf(dots[m] - mx); sum += e; dots[m] = e; }
    float inv = 1.f / sum;
    float o[16];
#pragma unroll
    for (int d = 0; d < 16; d++) o[d] = 0.f;
#pragma unroll
    for (int m = 0; m < 64; m++) {
        float p = dots[m] * inv;
#pragma unroll
        for (int d = 0; d < 16; d++) o[d] += p * sV[m * 16 + d];
    }
#pragma unroll
    for (int d = 0; d < 16; d++)
        low[((size_t)(bb * CDIM + head * 16 + d) * HDIM + hq) * WDIM + wq] = o[d];
}

// ---------------- channel mean/max pool --------------------------------------
__global__ void pool_kernel(const float* __restrict__ low, const float* __restrict__ high,
                            float* __restrict__ pool)
{
    int p = blockIdx.x * 256 + threadIdx.x;
    int bb = blockIdx.y;
    const float* lb = low  + (size_t)bb * CDIM * HW;
    const float* hb = high + (size_t)bb * CDIM * HW;
    float s = 0.f, mx = -1e30f;
    for (int c = 0; c < CDIM; c++) {
        float v = lb[c * HW + p] + hb[c * HW + p];
        s += v; mx = fmaxf(mx, v);
    }
    pool[(bb * 2 + 0) * HW + p] = s * (1.f / 256.f);
    pool[(bb * 2 + 1) * HW + p] = mx;
}

// ---------------- hybrid 7x7 conv (2->2) + sigmoid ---------------------------
__global__ void hybrid_kernel(const float* __restrict__ pool, const float* __restrict__ hw,
                              const float* __restrict__ hb, float* __restrict__ sig)
{
    __shared__ float sw[196];
    __shared__ float sb[2];
    int t = threadIdx.x;
    if (t < 196) sw[t] = hw[t];
    if (t < 2) sb[t] = hb[t];
    __syncthreads();
    int p = blockIdx.x * 256 + t;
    int bb = blockIdx.y;
    int h = p >> 7, w = p & 127;
#pragma unroll
    for (int oc = 0; oc < 2; oc++) {
        float acc = sb[oc];
#pragma unroll
        for (int ic = 0; ic < 2; ic++)
            for (int ky = 0; ky < 7; ky++) {
                int hy = h + ky - 3;
                if (hy < 0 || hy >= HDIM) continue;
                for (int kx = 0; kx < 7; kx++) {
                    int wx = w + kx - 3;
                    if (wx < 0 || wx >= WDIM) continue;
                    acc += pool[(bb * 2 + ic) * HW + hy * WDIM + wx] * sw[((oc * 2 + ic) * 7 + ky) * 7 + kx];
                }
            }
        sig[(bb * 2 + oc) * HW + p] = 1.f / (1.f + __expf(-acc));
    }
}

// ---------------- mix (tf32-rounded output: feeds smooth conv only) ----------
__global__ void mix_kernel(const float* __restrict__ low, const float* __restrict__ high,
                           const float* __restrict__ sig, float* __restrict__ out)
{
    int idx = blockIdx.x * 256 + threadIdx.x;
    int p = idx & (HW - 1);
    int bb = idx >> 22;
    float s0 = sig[(bb * 2 + 0) * HW + p];
    float s1 = sig[(bb * 2 + 1) * HW + p];
    out[idx] = f2tf(low[idx] * s0 + high[idx] * s1);
}

// ---------------- depthwise 7x7 + BN (tf32-rounded output: feeds pw GEMM) ----
__global__ void dw_kernel(const float* __restrict__ in, const float* __restrict__ w,
                          const float* __restrict__ bng, const float* __restrict__ bnb,
                          const float* __restrict__ bnm, const float* __restrict__ bnv,
                          float* __restrict__ out)
{
    __shared__ float sT[14 * 38];
    __shared__ float sWc[49];
    const int w0 = blockIdx.x * 32;
    const int h0 = blockIdx.y * 8;
    const int bc = blockIdx.z;
    const int c = bc & 255;
    const int tx = threadIdx.x, ty = threadIdx.y;
    const int t = ty * 32 + tx;
    if (t < 49) sWc[t] = w[c * 49 + t];
    const float* inb = in + (size_t)bc * HW;
    for (int e = t; e < 14 * 38; e += 256) {
        int row = e / 38, cc = e % 38;
        int h = h0 + row - 3, ww = w0 + cc - 3;
        float v = 0.f;
        if (h >= 0 && h < HDIM && ww >= 0 && ww < WDIM) v = inb[h * WDIM + ww];
        sT[e] = v;
    }
    __syncthreads();
    float acc = 0.f;
#pragma unroll
    for (int ky = 0; ky < 7; ky++)
#pragma unroll
        for (int kx = 0; kx < 7; kx++)
            acc += sT[(ty + ky) * 38 + tx + kx] * sWc[ky * 7 + kx];
    float sc = bng[c] * rsqrtf(bnv[c] + EPS);
    float sh = bnb[c] - bnm[c] * sc;
    out[(size_t)bc * HW + (h0 + ty) * WDIM + w0 + tx] = f2tf(acc * sc + sh);
}

// ---------------- launch ------------------------------------------------------
extern "C" void kernel_launch(void* const* d_in, const int* in_sizes, int n_in,
                              void* d_out, int out_size)
{
    const float* x        = (const float*)d_in[0];
    const float* qkv_w    = (const float*)d_in[1];
    const float* local1_w = (const float*)d_in[2];
    const float* l1g = (const float*)d_in[3];
    const float* l1b = (const float*)d_in[4];
    const float* l1m = (const float*)d_in[5];
    const float* l1v = (const float*)d_in[6];
    const float* local2_w = (const float*)d_in[7];
    const float* l2g = (const float*)d_in[8];
    const float* l2b = (const float*)d_in[9];
    const float* l2m = (const float*)d_in[10];
    const float* l2v = (const float*)d_in[11];
    const float* rel_table = (const float*)d_in[12];
    const float* hybrid_w  = (const float*)d_in[13];
    const float* hybrid_b  = (const float*)d_in[14];
    const float* smooth_w  = (const float*)d_in[15];
    const float* smg = (const float*)d_in[16];
    const float* smb = (const float*)d_in[17];
    const float* smm = (const float*)d_in[18];
    const float* smv = (const float*)d_in[19];
    const float* proj_dw_w = (const float*)d_in[20];
    const float* prg = (const float*)d_in[21];
    const float* prb = (const float*)d_in[22];
    const float* prm = (const float*)d_in[23];
    const float* prv = (const float*)d_in[24];
    const float* proj_pw_w = (const float*)d_in[25];

    float *p_qh, *p_kh, *p_high, *p_qkv, *p_low, *p_mix, *p_sm, *p_dw, *p_pool, *p_sig;
    float *p_xr, *p_w5t, *p_w3t, *p_wq, *p_w2, *p_wp;
    cudaGetSymbolAddress((void**)&p_qh,   g_qh);
    cudaGetSymbolAddress((void**)&p_kh,   g_kh);
    cudaGetSymbolAddress((void**)&p_high, g_high);
    cudaGetSymbolAddress((void**)&p_qkv,  g_qkv);
    cudaGetSymbolAddress((void**)&p_low,  g_low);
    cudaGetSymbolAddress((void**)&p_mix,  g_mix);
    cudaGetSymbolAddress((void**)&p_sm,   g_sm);
    cudaGetSymbolAddress((void**)&p_dw,   g_dw);
    cudaGetSymbolAddress((void**)&p_pool, g_pool);
    cudaGetSymbolAddress((void**)&p_sig,  g_sig);
    cudaGetSymbolAddress((void**)&p_xr,   g_xr);
    cudaGetSymbolAddress((void**)&p_w5t,  g_w5t);
    cudaGetSymbolAddress((void**)&p_w3t,  g_w3t);
    cudaGetSymbolAddress((void**)&p_wq,   g_wq);
    cudaGetSymbolAddress((void**)&p_w2,   g_w2);
    cudaGetSymbolAddress((void**)&p_wp,   g_wp);

    const int smem3 = (2 * (8 * 10 * 36 + 9  * 512)) * 4;   // 59904 B
    const int smem5 = (2 * (8 * 12 * 38 + 25 * 512)) * 4;   // 131584 B
    const int smemG = (2 * (GEM_XF + GEM_WF)) * 4;          // 86016 B
    cudaFuncSetAttribute(conv_mma<5, false>, cudaFuncAttributeMaxDynamicSharedMemorySize, smem5);
    cudaFuncSetAttribute(conv_mma<3, true>,  cudaFuncAttributeMaxDynamicSharedMemorySize, smem3);
    cudaFuncSetAttribute(gemm1x1_mma,        cudaFuncAttributeMaxDynamicSharedMemorySize, smemG);

    // ---- pre-pass: tf32 rounding + weight layout transform ----
    int nx = BDIM * CDIM * HW;
    round_copy<<<(nx + 255) / 256, 256>>>(x, p_xr, nx);
    round_copy<<<(3 * CDIM * CDIM + 255) / 256, 256>>>(qkv_w, p_wq, 3 * CDIM * CDIM);
    round_copy<<<(CDIM * CDIM + 255) / 256, 256>>>(local2_w, p_w2, CDIM * CDIM);
    round_copy<<<(CDIM * CDIM + 255) / 256, 256>>>(proj_pw_w, p_wp, CDIM * CDIM);
    wtransform<9><<<(CDIM * CDIM * 9 + 255) / 256, 256>>>(local1_w, p_w3t);
    wtransform<25><<<(CDIM * CDIM * 25 + 255) / 256, 256>>>(smooth_w, p_w5t);

    // ---- main chain ----
    gemm1x1_mma<<<dim3(64, 12, 4), 256, smemG>>>(p_xr, p_wq, nullptr, nullptr, nullptr, nullptr, p_qkv, 768);
    gemm1x1_mma<<<dim3(64, 4, 4), 256, smemG>>>(p_xr, p_w2, l2g, l2b, l2m, l2v, p_kh, 256);
    conv_mma<3, true><<<dim3(4, 16, 16), 256, smem3>>>(p_xr, p_w3t, l1g, l1b, l1m, l1v,
                                                       p_qh, p_kh, p_high);
    attn_kernel<<<dim3(256, 16, 4), 64>>>(p_qkv, p_qh, p_kh, rel_table, p_low);
    pool_kernel<<<dim3(64, 4), 256>>>(p_low, p_high, p_pool);
    hybrid_kernel<<<dim3(64, 4), 256>>>(p_pool, hybrid_w, hybrid_b, p_sig);
    mix_kernel<<<dim3(BDIM * CDIM * HW / 256), 256>>>(p_low, p_high, p_sig, p_mix);
    conv_mma<5, false><<<dim3(4, 16, 16), 256, smem5>>>(p_mix, p_w5t, smg, smb, smm, smv,
                                                        p_sm, nullptr, nullptr);
    dw_kernel<<<dim3(4, 16, 1024), dim3(32, 8)>>>(p_sm, proj_dw_w, prg, prb, prm, prv, p_dw);
    gemm1x1_mma<<<dim3(64, 4, 4), 256, smemG>>>(p_dw, p_wp, nullptr, nullptr, nullptr, nullptr,
                                                (float*)d_out, 256);
}